// round 1
// baseline (speedup 1.0000x reference)
#include <cuda_runtime.h>
#include <math.h>

#define B_   4096
#define N_   32768
#define D_   1024
#define BM   128
#define BN   128
#define BK   16
#define TM   8
#define TN   8
#define NBLK (N_ / BN)   // 256
#define BBLK (B_ / BM)   // 32

// Scratch (no allocations allowed -> device globals)
__device__ float  g_qinv[B_];
__device__ float  g_kinv[N_];
__device__ float4 g_part[(size_t)B_ * NBLK];   // (max, idx-as-float, sum, sumsq) : 16 MB
__device__ float  g_var[B_];

// ---------------------------------------------------------------------------
// Kernel 1: per-row inverse L2 norm:  inv[r] = 1 / max(||x_r||, 1e-12)
// ---------------------------------------------------------------------------
__global__ void inv_norm_kernel(const float* __restrict__ x, float* __restrict__ inv)
{
    const int row = blockIdx.x;
    const float4* xr = reinterpret_cast<const float4*>(x + (size_t)row * D_);
    float s = 0.f;
    for (int i = threadIdx.x; i < D_ / 4; i += blockDim.x) {
        float4 v = xr[i];
        s += v.x * v.x + v.y * v.y + v.z * v.z + v.w * v.w;
    }
    __shared__ float sm[256];
    sm[threadIdx.x] = s;
    __syncthreads();
    for (int off = 128; off > 0; off >>= 1) {
        if (threadIdx.x < off) sm[threadIdx.x] += sm[threadIdx.x + off];
        __syncthreads();
    }
    if (threadIdx.x == 0)
        inv[row] = 1.0f / fmaxf(sqrtf(sm[0]), 1e-12f);
}

// ---------------------------------------------------------------------------
// Kernel 2: fp32 GEMM block (128x128) with fused per-row reduction.
// Grid: (NBLK, BBLK), 256 threads, each thread owns an 8x8 accumulator tile.
// Epilogue: scale by qinv*kinv, reduce {max,argmax,sum,sumsq} over the 128
// columns of the block, write one float4 partial per (row, nblock).
// ---------------------------------------------------------------------------
__global__ __launch_bounds__(256, 2)
void sim_kernel(const float* __restrict__ Q, const float* __restrict__ K)
{
    __shared__ float As[BK][BM];
    __shared__ float Bs[BK][BN];

    const int tid  = threadIdx.x;
    const int tx   = tid & 15;        // 0..15 -> column group
    const int ty   = tid >> 4;        // 0..15 -> row group
    const int nblk = blockIdx.x;
    const int bblk = blockIdx.y;

    const float* Qb = Q + (size_t)bblk * BM * D_;
    const float* Kb = K + (size_t)nblk * BN * D_;

    float acc[TM][TN];
#pragma unroll
    for (int i = 0; i < TM; i++)
#pragma unroll
        for (int j = 0; j < TN; j++) acc[i][j] = 0.f;

    // Each thread loads 2 float4 for A-tile and 2 for B-tile per k-step.
    const int li0  = tid * 2;
    const int row0 = li0 >> 2;            // 0..127  (li0, li0+1 share or adjacent)
    const int k40  = (li0 & 3) * 4;       // 0 or 8
    const int row1 = (li0 + 1) >> 2;
    const int k41  = ((li0 + 1) & 3) * 4;

    // prefetch first tile
    float4 pa0 = *reinterpret_cast<const float4*>(Qb + (size_t)row0 * D_ + k40);
    float4 pa1 = *reinterpret_cast<const float4*>(Qb + (size_t)row1 * D_ + k41);
    float4 pb0 = *reinterpret_cast<const float4*>(Kb + (size_t)row0 * D_ + k40);
    float4 pb1 = *reinterpret_cast<const float4*>(Kb + (size_t)row1 * D_ + k41);

    for (int k0 = 0; k0 < D_; k0 += BK) {
        // commit prefetched tile to SMEM (transposed: As[k][m])
        As[k40 + 0][row0] = pa0.x; As[k40 + 1][row0] = pa0.y;
        As[k40 + 2][row0] = pa0.z; As[k40 + 3][row0] = pa0.w;
        As[k41 + 0][row1] = pa1.x; As[k41 + 1][row1] = pa1.y;
        As[k41 + 2][row1] = pa1.z; As[k41 + 3][row1] = pa1.w;
        Bs[k40 + 0][row0] = pb0.x; Bs[k40 + 1][row0] = pb0.y;
        Bs[k40 + 2][row0] = pb0.z; Bs[k40 + 3][row0] = pb0.w;
        Bs[k41 + 0][row1] = pb1.x; Bs[k41 + 1][row1] = pb1.y;
        Bs[k41 + 2][row1] = pb1.z; Bs[k41 + 3][row1] = pb1.w;
        __syncthreads();

        // prefetch next tile while computing this one
        const int kn = k0 + BK;
        if (kn < D_) {
            pa0 = *reinterpret_cast<const float4*>(Qb + (size_t)row0 * D_ + kn + k40);
            pa1 = *reinterpret_cast<const float4*>(Qb + (size_t)row1 * D_ + kn + k41);
            pb0 = *reinterpret_cast<const float4*>(Kb + (size_t)row0 * D_ + kn + k40);
            pb1 = *reinterpret_cast<const float4*>(Kb + (size_t)row1 * D_ + kn + k41);
        }

#pragma unroll
        for (int kk = 0; kk < BK; kk++) {
            float4 a0 = *reinterpret_cast<const float4*>(&As[kk][ty * TM]);
            float4 a1 = *reinterpret_cast<const float4*>(&As[kk][ty * TM + 4]);
            float4 b0 = *reinterpret_cast<const float4*>(&Bs[kk][tx * TN]);
            float4 b1 = *reinterpret_cast<const float4*>(&Bs[kk][tx * TN + 4]);
            float a[TM] = {a0.x, a0.y, a0.z, a0.w, a1.x, a1.y, a1.z, a1.w};
            float b[TN] = {b0.x, b0.y, b0.z, b0.w, b1.x, b1.y, b1.z, b1.w};
#pragma unroll
            for (int i = 0; i < TM; i++)
#pragma unroll
                for (int j = 0; j < TN; j++)
                    acc[i][j] = fmaf(a[i], b[j], acc[i][j]);
        }
        __syncthreads();
    }

    // ------------------------- fused epilogue ------------------------------
    const int gc0 = nblk * BN + tx * TN;
    float kv[TN];
#pragma unroll
    for (int j = 0; j < TN; j++) kv[j] = g_kinv[gc0 + j];

#pragma unroll
    for (int i = 0; i < TM; i++) {
        const int gr = bblk * BM + ty * TM + i;
        const float qv = g_qinv[gr];
        float mx = -1e30f;
        int   mi = 0x7fffffff;
        float sum = 0.f, sq = 0.f;
#pragma unroll
        for (int j = 0; j < TN; j++) {
            float s = acc[i][j] * qv * kv[j];
            sum += s;
            sq  = fmaf(s, s, sq);
            if (s > mx) { mx = s; mi = gc0 + j; }   // ascending j -> keeps lowest idx on tie
        }
        // reduce across the 16 column-group threads (same ty) via half-warp shuffles
#pragma unroll
        for (int m = 1; m < 16; m <<= 1) {
            float omx  = __shfl_xor_sync(0xffffffffu, mx,  m);
            int   omi  = __shfl_xor_sync(0xffffffffu, mi,  m);
            float osum = __shfl_xor_sync(0xffffffffu, sum, m);
            float osq  = __shfl_xor_sync(0xffffffffu, sq,  m);
            sum += osum;
            sq  += osq;
            if (omx > mx || (omx == mx && omi < mi)) { mx = omx; mi = omi; }
        }
        if (tx == 0)
            g_part[(size_t)gr * NBLK + nblk] =
                make_float4(mx, __int_as_float(mi), sum, sq);
    }
}

// ---------------------------------------------------------------------------
// Kernel 3: per-row final reduce over 256 partials, gather values[best],
//           per-row unbiased variance.
// ---------------------------------------------------------------------------
__global__ void finalize_kernel(const float* __restrict__ V, float* __restrict__ out)
{
    const int row = blockIdx.x;
    const int tid = threadIdx.x;   // 256 threads == NBLK

    float4 p = g_part[(size_t)row * NBLK + tid];
    __shared__ float smx[256];
    __shared__ int   smi[256];
    __shared__ float ssum[256];
    __shared__ float ssq[256];
    smx[tid] = p.x;
    smi[tid] = __float_as_int(p.y);
    ssum[tid] = p.z;
    ssq[tid]  = p.w;
    __syncthreads();

    for (int off = 128; off > 0; off >>= 1) {
        if (tid < off) {
            ssum[tid] += ssum[tid + off];
            ssq[tid]  += ssq[tid + off];
            float om = smx[tid + off];
            int   oi = smi[tid + off];
            if (om > smx[tid] || (om == smx[tid] && oi < smi[tid])) {
                smx[tid] = om;
                smi[tid] = oi;
            }
        }
        __syncthreads();
    }

    if (tid == 0) {
        float s = ssum[0], q2 = ssq[0];
        g_var[row] = (q2 - s * s / (float)N_) / (float)(N_ - 1);
    }

    const int best = smi[0];
    const float4* vv = reinterpret_cast<const float4*>(V + (size_t)best * D_);
    float4* o = reinterpret_cast<float4*>(out + (size_t)row * D_);
    o[tid] = vv[tid];   // 256 * float4 = 1024 floats
}

// ---------------------------------------------------------------------------
// Kernel 4: deterministic mean of row variances -> out[B*D]
// ---------------------------------------------------------------------------
__global__ void var_mean_kernel(float* __restrict__ out)
{
    __shared__ float sm[1024];
    const int tid = threadIdx.x;
    sm[tid] = g_var[tid] + g_var[tid + 1024] + g_var[tid + 2048] + g_var[tid + 3072];
    __syncthreads();
    for (int off = 512; off > 0; off >>= 1) {
        if (tid < off) sm[tid] += sm[tid + off];
        __syncthreads();
    }
    if (tid == 0)
        out[(size_t)B_ * D_] = sm[0] / (float)B_;
}

// ---------------------------------------------------------------------------
extern "C" void kernel_launch(void* const* d_in, const int* in_sizes, int n_in,
                              void* d_out, int out_size)
{
    const float* query  = (const float*)d_in[0];   // [4096, 1024]
    const float* keys   = (const float*)d_in[1];   // [32768, 1024]
    const float* values = (const float*)d_in[2];   // [32768, 1024]
    float* out = (float*)d_out;                    // [4096*1024 + 1]

    float* qinv; cudaGetSymbolAddress((void**)&qinv, g_qinv);
    float* kinv; cudaGetSymbolAddress((void**)&kinv, g_kinv);

    inv_norm_kernel<<<B_, 256>>>(query, qinv);
    inv_norm_kernel<<<N_, 256>>>(keys,  kinv);

    dim3 grid(NBLK, BBLK);
    sim_kernel<<<grid, 256>>>(query, keys);

    finalize_kernel<<<B_, 256>>>(values, out);
    var_mean_kernel<<<1, 1024>>>(out);
}

// round 3
// speedup vs baseline: 4.2599x; 4.2599x over previous
#include <cuda_runtime.h>
#include <cuda_bf16.h>
#include <cstdint>
#include <math.h>

#define B_   4096
#define N_   32768
#define D_   1024
#define BM   128
#define BN   128
#define KC   64                  // K elems per chunk (64 bf16 = 128 B = SW128 row)
#define NCH  (D_ / KC)           // 16
#define NBLK (N_ / BN)           // 256
#define BBLK (B_ / BM)           // 32

#define TILE_B  16384            // 128 rows x 128 B
#define STAGE_B (3 * TILE_B)     // A(qh), Bh(kh), Bl(kl)
#define SMEM_DYN (2 * STAGE_B)   // 96 KB double buffer

// ---------------- device-global scratch ------------------------------------
__device__ float          g_qinv[B_];
__device__ float          g_kinv[N_];
__device__ __nv_bfloat16  g_qh[(size_t)B_ * D_];
__device__ __nv_bfloat16  g_kh[(size_t)N_ * D_];
__device__ __nv_bfloat16  g_kl[(size_t)N_ * D_];
__device__ float4         g_topA[(size_t)B_ * NBLK];  // v0,i0,v1,i1
__device__ float2         g_topB[(size_t)B_ * NBLK];  // v2,i2
__device__ float2         g_ms  [(size_t)B_ * NBLK];  // sum,sumsq
__device__ float          g_var[B_];
__device__ int4           g_cand[B_];

// ---------------- helpers ---------------------------------------------------
__device__ __forceinline__ uint32_t smem_u32(const void* p) {
    uint32_t a;
    asm("{ .reg .u64 t; cvta.to.shared.u64 t, %1; cvt.u32.u64 %0, t; }" : "=r"(a) : "l"(p));
    return a;
}
__device__ __forceinline__ void ldsm4(uint32_t* r, uint32_t addr) {
    asm volatile("ldmatrix.sync.aligned.m8n8.x4.shared.b16 {%0,%1,%2,%3}, [%4];"
                 : "=r"(r[0]), "=r"(r[1]), "=r"(r[2]), "=r"(r[3]) : "r"(addr));
}
__device__ __forceinline__ void mma16816(float* c, const uint32_t* a, const uint32_t* b) {
    asm volatile("mma.sync.aligned.m16n8k16.row.col.f32.bf16.bf16.f32 "
                 "{%0,%1,%2,%3}, {%4,%5,%6,%7}, {%8,%9}, {%0,%1,%2,%3};"
                 : "+f"(c[0]), "+f"(c[1]), "+f"(c[2]), "+f"(c[3])
                 : "r"(a[0]), "r"(a[1]), "r"(a[2]), "r"(a[3]), "r"(b[0]), "r"(b[1]));
}
__device__ __forceinline__ void top3_ins(float v, int i,
                                         float& v0, int& i0, float& v1, int& i1,
                                         float& v2, int& i2) {
    if (v > v0)      { v2 = v1; i2 = i1; v1 = v0; i1 = i0; v0 = v; i0 = i; }
    else if (v > v1) { v2 = v1; i2 = i1; v1 = v;  i1 = i; }
    else if (v > v2) { v2 = v;  i2 = i; }
}

// ---------------------------------------------------------------------------
// Kernel 1a: query prep -> qinv + bf16(q_hat)
// ---------------------------------------------------------------------------
__global__ void prep_q_kernel(const float* __restrict__ x)
{
    const int row = blockIdx.x;
    const int tid = threadIdx.x;   // 256
    float4 v = reinterpret_cast<const float4*>(x + (size_t)row * D_)[tid];
    float s = v.x * v.x + v.y * v.y + v.z * v.z + v.w * v.w;
    __shared__ float sm[256];
    sm[tid] = s;
    __syncthreads();
    for (int o = 128; o > 0; o >>= 1) {
        if (tid < o) sm[tid] += sm[tid + o];
        __syncthreads();
    }
    const float inv = 1.0f / fmaxf(sqrtf(sm[0]), 1e-12f);
    if (tid == 0) g_qinv[row] = inv;

    float q[4] = {v.x * inv, v.y * inv, v.z * inv, v.w * inv};
    uint32_t hp[2];
#pragma unroll
    for (int p = 0; p < 2; p++) {
        __nv_bfloat16 h0 = __float2bfloat16(q[2 * p]);
        __nv_bfloat16 h1 = __float2bfloat16(q[2 * p + 1]);
        hp[p] = (uint32_t)__bfloat16_as_ushort(h0) | ((uint32_t)__bfloat16_as_ushort(h1) << 16);
    }
    reinterpret_cast<uint2*>(g_qh + (size_t)row * D_)[tid] = make_uint2(hp[0], hp[1]);
}

// ---------------------------------------------------------------------------
// Kernel 1b: key prep -> kinv + bf16 hi/lo split of k_hat
// ---------------------------------------------------------------------------
__global__ void prep_k_kernel(const float* __restrict__ x)
{
    const int row = blockIdx.x;
    const int tid = threadIdx.x;
    float4 v = reinterpret_cast<const float4*>(x + (size_t)row * D_)[tid];
    float s = v.x * v.x + v.y * v.y + v.z * v.z + v.w * v.w;
    __shared__ float sm[256];
    sm[tid] = s;
    __syncthreads();
    for (int o = 128; o > 0; o >>= 1) {
        if (tid < o) sm[tid] += sm[tid + o];
        __syncthreads();
    }
    const float inv = 1.0f / fmaxf(sqrtf(sm[0]), 1e-12f);
    if (tid == 0) g_kinv[row] = inv;

    float q[4] = {v.x * inv, v.y * inv, v.z * inv, v.w * inv};
    uint32_t hp[2], lp[2];
#pragma unroll
    for (int p = 0; p < 2; p++) {
        __nv_bfloat16 h0 = __float2bfloat16(q[2 * p]);
        __nv_bfloat16 h1 = __float2bfloat16(q[2 * p + 1]);
        __nv_bfloat16 l0 = __float2bfloat16(q[2 * p] - __bfloat162float(h0));
        __nv_bfloat16 l1 = __float2bfloat16(q[2 * p + 1] - __bfloat162float(h1));
        hp[p] = (uint32_t)__bfloat16_as_ushort(h0) | ((uint32_t)__bfloat16_as_ushort(h1) << 16);
        lp[p] = (uint32_t)__bfloat16_as_ushort(l0) | ((uint32_t)__bfloat16_as_ushort(l1) << 16);
    }
    reinterpret_cast<uint2*>(g_kh + (size_t)row * D_)[tid] = make_uint2(hp[0], hp[1]);
    reinterpret_cast<uint2*>(g_kl + (size_t)row * D_)[tid] = make_uint2(lp[0], lp[1]);
}

// ---------------------------------------------------------------------------
// Kernel 2: mma.sync bf16 GEMM (128x128 tile) + fused top3/sum/sumsq
//   sim = qh . (kh + kl)   accumulated fp32
// ---------------------------------------------------------------------------
__global__ __launch_bounds__(256, 2)
void sim_kernel()
{
    extern __shared__ char dynsmem[];
    const uint32_t sbase = smem_u32(dynsmem);

    const int tid = threadIdx.x;
    const int l   = tid & 31;
    const int wid = tid >> 5;
    const int wm  = wid >> 2;      // 0..1
    const int wn  = wid & 3;       // 0..3
    const int nblk = blockIdx.x;
    const int bblk = blockIdx.y;

    const char* srcA = (const char*)(g_qh + (size_t)bblk * BM * D_);
    const char* srcH = (const char*)(g_kh + (size_t)nblk * BN * D_);
    const char* srcL = (const char*)(g_kl + (size_t)nblk * BN * D_);

    // ---- async tile loader (48 KB per chunk) ------------------------------
    auto load_chunk = [&](int c, int st) {
        const uint32_t stb = sbase + st * STAGE_B;
        const char* srcs[3] = {srcA, srcH, srcL};
#pragma unroll
        for (int i = 0; i < 12; i++) {
            const int t = i >> 2;
            const int w = (i & 3) * 256 + tid;
            const int r = w >> 3;
            const int j = w & 7;
            const char* g = srcs[t] + (size_t)r * (D_ * 2) + c * 128 + j * 16;
            uint32_t off = (uint32_t)(r * 128 + j * 16);
            uint32_t dst = stb + t * TILE_B + (off ^ ((off >> 3) & 0x70));
            asm volatile("cp.async.cg.shared.global [%0], [%1], 16;" :: "r"(dst), "l"(g));
        }
        asm volatile("cp.async.commit_group;" ::: "memory");
    };

    // ---- per-lane ldmatrix offsets ----------------------------------------
    const uint32_t rowA = l & 15;
    const uint32_t acs  = (l >> 4) * 16;
    const uint32_t xa   = (rowA & 7) << 4;
    const uint32_t aoff = rowA * 128 + (uint32_t)wm * 8192;   // wm*64 rows

    const uint32_t rowB = (l & 7) + ((l >> 4) << 3);
    const uint32_t bcs  = ((l >> 3) & 1) * 16;
    const uint32_t xb   = (rowB & 7) << 4;
    const uint32_t boff = rowB * 128 + (uint32_t)wn * 4096;   // wn*32 rows

    float acc[4][4][4];
#pragma unroll
    for (int m = 0; m < 4; m++)
#pragma unroll
        for (int n = 0; n < 4; n++)
#pragma unroll
            for (int e = 0; e < 4; e++) acc[m][n][e] = 0.f;

    load_chunk(0, 0);

    for (int c = 0; c < NCH; c++) {
        const int st = c & 1;
        if (c + 1 < NCH) {
            load_chunk(c + 1, st ^ 1);
            asm volatile("cp.async.wait_group 1;" ::: "memory");
        } else {
            asm volatile("cp.async.wait_group 0;" ::: "memory");
        }
        __syncthreads();

        const uint32_t TBa = sbase + st * STAGE_B + aoff;
        const uint32_t TBh = sbase + st * STAGE_B + TILE_B     + boff;
        const uint32_t TBl = sbase + st * STAGE_B + 2 * TILE_B + boff;

#pragma unroll
        for (int ks = 0; ks < 4; ks++) {
            const uint32_t ka = (32u * ks + acs) ^ xa;
            const uint32_t kb = (32u * ks + bcs) ^ xb;
            uint32_t af[4][4];
#pragma unroll
            for (int m = 0; m < 4; m++) ldsm4(af[m], TBa + m * 2048 + ka);

            uint32_t bh[4][2];
#pragma unroll
            for (int p = 0; p < 2; p++) {
                uint32_t t4[4];
                ldsm4(t4, TBh + p * 2048 + kb);
                bh[2 * p][0] = t4[0]; bh[2 * p][1] = t4[1];
                bh[2 * p + 1][0] = t4[2]; bh[2 * p + 1][1] = t4[3];
            }
#pragma unroll
            for (int m = 0; m < 4; m++)
#pragma unroll
                for (int n = 0; n < 4; n++) mma16816(acc[m][n], af[m], bh[n]);

            uint32_t bl[4][2];
#pragma unroll
            for (int p = 0; p < 2; p++) {
                uint32_t t4[4];
                ldsm4(t4, TBl + p * 2048 + kb);
                bl[2 * p][0] = t4[0]; bl[2 * p][1] = t4[1];
                bl[2 * p + 1][0] = t4[2]; bl[2 * p + 1][1] = t4[3];
            }
#pragma unroll
            for (int m = 0; m < 4; m++)
#pragma unroll
                for (int n = 0; n < 4; n++) mma16816(acc[m][n], af[m], bl[n]);
        }
        __syncthreads();
    }

    // ---- epilogue: per-row sum/sumsq/top3 ---------------------------------
    float* spart = reinterpret_cast<float*>(dynsmem);   // 128 rows x 4 nwarps x 8 f

#pragma unroll
    for (int m = 0; m < 4; m++) {
#pragma unroll
        for (int h = 0; h < 2; h++) {
            float sum = 0.f, sq = 0.f;
            float v0 = -2.f, v1 = -2.f, v2 = -2.f;
            int   i0 = 0, i1 = 0, i2 = 0;
            const int colbase = nblk * BN + wn * 32 + 2 * (l & 3);
#pragma unroll
            for (int n = 0; n < 4; n++) {
#pragma unroll
                for (int e = 0; e < 2; e++) {
                    const float v = acc[m][n][2 * h + e];
                    sum += v;
                    sq = fmaf(v, v, sq);
                    top3_ins(v, colbase + 8 * n + e, v0, i0, v1, i1, v2, i2);
                }
            }
#pragma unroll
            for (int o = 1; o <= 2; o <<= 1) {
                float ov0 = __shfl_xor_sync(0xffffffffu, v0, o);
                float ov1 = __shfl_xor_sync(0xffffffffu, v1, o);
                float ov2 = __shfl_xor_sync(0xffffffffu, v2, o);
                int   oi0 = __shfl_xor_sync(0xffffffffu, i0, o);
                int   oi1 = __shfl_xor_sync(0xffffffffu, i1, o);
                int   oi2 = __shfl_xor_sync(0xffffffffu, i2, o);
                sum += __shfl_xor_sync(0xffffffffu, sum, o);
                sq  += __shfl_xor_sync(0xffffffffu, sq, o);
                top3_ins(ov0, oi0, v0, i0, v1, i1, v2, i2);
                top3_ins(ov1, oi1, v0, i0, v1, i1, v2, i2);
                top3_ins(ov2, oi2, v0, i0, v1, i1, v2, i2);
            }
            if ((l & 3) == 0) {
                const int rloc = wm * 64 + 16 * m + (l >> 2) + 8 * h;
                float* p = spart + (rloc * 4 + wn) * 8;
                p[0] = sum; p[1] = sq;
                p[2] = v0;  p[3] = v1;  p[4] = v2;
                p[5] = __int_as_float(i0);
                p[6] = __int_as_float(i1);
                p[7] = __int_as_float(i2);
            }
        }
    }
    __syncthreads();

    if (tid < 128) {
        float sum = 0.f, sq = 0.f;
        float v0 = -2.f, v1 = -2.f, v2 = -2.f;
        int   i0 = 0, i1 = 0, i2 = 0;
#pragma unroll
        for (int w = 0; w < 4; w++) {
            const float* p = spart + (tid * 4 + w) * 8;
            sum += p[0]; sq += p[1];
            top3_ins(p[2], __float_as_int(p[5]), v0, i0, v1, i1, v2, i2);
            top3_ins(p[3], __float_as_int(p[6]), v0, i0, v1, i1, v2, i2);
            top3_ins(p[4], __float_as_int(p[7]), v0, i0, v1, i1, v2, i2);
        }
        const int gr = bblk * BM + tid;
        const size_t o = (size_t)gr * NBLK + nblk;
        g_ms[o]   = make_float2(sum, sq);
        g_topA[o] = make_float4(v0, __int_as_float(i0), v1, __int_as_float(i1));
        g_topB[o] = make_float2(v2, __int_as_float(i2));
    }
}

// ---------------------------------------------------------------------------
// Kernel 3: reduce 256 block-partials per row -> variance + global top-3
// ---------------------------------------------------------------------------
__global__ void finalize_kernel()
{
    const int row = blockIdx.x;
    const int tid = threadIdx.x;   // 256 == NBLK

    __shared__ float4 sA[256];
    __shared__ float2 sB[256];
    __shared__ float2 sM[256];
    const size_t o = (size_t)row * NBLK + tid;
    sA[tid] = g_topA[o];
    sB[tid] = g_topB[o];
    sM[tid] = g_ms[o];
    __syncthreads();

    for (int off = 128; off > 0; off >>= 1) {
        if (tid < off) {
            float4 a = sA[tid]; float2 a2 = sB[tid];
            float4 b = sA[tid + off]; float2 b2 = sB[tid + off];
            float v0 = a.x, v1 = a.z, v2 = a2.x;
            int   i0 = __float_as_int(a.y), i1 = __float_as_int(a.w),
                  i2 = __float_as_int(a2.y);
            top3_ins(b.x,  __float_as_int(b.y),  v0, i0, v1, i1, v2, i2);
            top3_ins(b.z,  __float_as_int(b.w),  v0, i0, v1, i1, v2, i2);
            top3_ins(b2.x, __float_as_int(b2.y), v0, i0, v1, i1, v2, i2);
            sA[tid] = make_float4(v0, __int_as_float(i0), v1, __int_as_float(i1));
            sB[tid] = make_float2(v2, __int_as_float(i2));
            float2 x = sM[tid], y = sM[tid + off];
            sM[tid] = make_float2(x.x + y.x, x.y + y.y);
        }
        __syncthreads();
    }
    if (tid == 0) {
        const float s = sM[0].x, q2 = sM[0].y;
        g_var[row] = (q2 - s * s / (float)N_) / (float)(N_ - 1);
        g_cand[row] = make_int4(__float_as_int(sA[0].y), __float_as_int(sA[0].w),
                                __float_as_int(sB[0].y), 0);
    }
}

// ---------------------------------------------------------------------------
// Kernel 4: exact fp32 rescore of 3 candidates + gather values[best]
// ---------------------------------------------------------------------------
__global__ void rescore_kernel(const float* __restrict__ Q, const float* __restrict__ K,
                               const float* __restrict__ V, float* __restrict__ out)
{
    const int row = blockIdx.x;
    const int tid = threadIdx.x;   // 256
    const int4 cd = g_cand[row];
    const float qi = g_qinv[row];

    float4 q = reinterpret_cast<const float4*>(Q + (size_t)row * D_)[tid];
    q.x *= qi; q.y *= qi; q.z *= qi; q.w *= qi;

    __shared__ float r[3][256];
    __shared__ int sbest;
    const int cands[3] = {cd.x, cd.y, cd.z};
#pragma unroll
    for (int c = 0; c < 3; c++) {
        const float ki = g_kinv[cands[c]];
        float4 k = reinterpret_cast<const float4*>(K + (size_t)cands[c] * D_)[tid];
        r[c][tid] = (q.x * k.x + q.y * k.y + q.z * k.z + q.w * k.w) * ki;
    }
    __syncthreads();
    for (int off = 128; off > 0; off >>= 1) {
        if (tid < off) {
            r[0][tid] += r[0][tid + off];
            r[1][tid] += r[1][tid + off];
            r[2][tid] += r[2][tid + off];
        }
        __syncthreads();
    }
    if (tid == 0) {
        float bv = r[0][0]; int bi = cands[0];
        for (int c = 1; c < 3; c++) {
            const float v = r[c][0];
            if (v > bv || (v == bv && cands[c] < bi)) { bv = v; bi = cands[c]; }
        }
        sbest = bi;
    }
    __syncthreads();
    reinterpret_cast<float4*>(out + (size_t)row * D_)[tid] =
        reinterpret_cast<const float4*>(V + (size_t)sbest * D_)[tid];
}

// ---------------------------------------------------------------------------
// Kernel 5: deterministic mean of row variances -> out[B*D]
// ---------------------------------------------------------------------------
__global__ void var_mean_kernel(float* __restrict__ out)
{
    __shared__ float sm[1024];
    const int tid = threadIdx.x;
    sm[tid] = g_var[tid] + g_var[tid + 1024] + g_var[tid + 2048] + g_var[tid + 3072];
    __syncthreads();
    for (int o = 512; o > 0; o >>= 1) {
        if (tid < o) sm[tid] += sm[tid + o];
        __syncthreads();
    }
    if (tid == 0) out[(size_t)B_ * D_] = sm[0] / (float)B_;
}

// ---------------------------------------------------------------------------
extern "C" void kernel_launch(void* const* d_in, const int* in_sizes, int n_in,
                              void* d_out, int out_size)
{
    const float* query  = (const float*)d_in[0];
    const float* keys   = (const float*)d_in[1];
    const float* values = (const float*)d_in[2];
    float* out = (float*)d_out;

    cudaFuncSetAttribute(sim_kernel, cudaFuncAttributeMaxDynamicSharedMemorySize, SMEM_DYN);

    prep_q_kernel<<<B_, 256>>>(query);
    prep_k_kernel<<<N_, 256>>>(keys);

    sim_kernel<<<dim3(NBLK, BBLK), 256, SMEM_DYN>>>();

    finalize_kernel<<<B_, 256>>>();
    rescore_kernel<<<B_, 256>>>(query, keys, values, out);
    var_mean_kernel<<<1, 1024>>>(out);
}

// round 4
// speedup vs baseline: 6.6439x; 1.5596x over previous
#include <cuda_runtime.h>
#include <cuda_fp16.h>
#include <cstdint>
#include <math.h>

#define B_   4096
#define N_   32768
#define D_   1024
#define BM   128
#define BN   128
#define KC   64                  // K elems per chunk (64 fp16 = 128 B row)
#define NCH  (D_ / KC)           // 16
#define NBLK (N_ / BN)           // 256
#define BBLK (B_ / BM)           // 32

#define TILE_B  16384            // 128 rows x 128 B
#define STAGE_B (2 * TILE_B)     // A(q), B(k)
#define SMEM_DYN (2 * STAGE_B)   // 64 KB double buffer

// ---------------- device-global scratch ------------------------------------
__device__ float   g_qinv[B_];
__device__ float   g_kinv[N_];
__device__ __half  g_qh[(size_t)B_ * D_];
__device__ __half  g_kh[(size_t)N_ * D_];
__device__ float4  g_topA[(size_t)B_ * NBLK];  // v0,i0,v1,i1
__device__ float2  g_topB[(size_t)B_ * NBLK];  // v2,i2
__device__ float2  g_ms  [(size_t)B_ * NBLK];  // sum,sumsq
__device__ float   g_var[B_];
__device__ int4    g_cand[B_];

// ---------------- helpers ---------------------------------------------------
__device__ __forceinline__ uint32_t smem_u32(const void* p) {
    uint32_t a;
    asm("{ .reg .u64 t; cvta.to.shared.u64 t, %1; cvt.u32.u64 %0, t; }" : "=r"(a) : "l"(p));
    return a;
}
__device__ __forceinline__ void ldsm4(uint32_t* r, uint32_t addr) {
    asm volatile("ldmatrix.sync.aligned.m8n8.x4.shared.b16 {%0,%1,%2,%3}, [%4];"
                 : "=r"(r[0]), "=r"(r[1]), "=r"(r[2]), "=r"(r[3]) : "r"(addr));
}
__device__ __forceinline__ void mma16816(float* c, const uint32_t* a, const uint32_t* b) {
    asm volatile("mma.sync.aligned.m16n8k16.row.col.f32.f16.f16.f32 "
                 "{%0,%1,%2,%3}, {%4,%5,%6,%7}, {%8,%9}, {%0,%1,%2,%3};"
                 : "+f"(c[0]), "+f"(c[1]), "+f"(c[2]), "+f"(c[3])
                 : "r"(a[0]), "r"(a[1]), "r"(a[2]), "r"(a[3]), "r"(b[0]), "r"(b[1]));
}
__device__ __forceinline__ void top3_ins(float v, int i,
                                         float& v0, int& i0, float& v1, int& i1,
                                         float& v2, int& i2) {
    if (v > v0)      { v2 = v1; i2 = i1; v1 = v0; i1 = i0; v0 = v; i0 = i; }
    else if (v > v1) { v2 = v1; i2 = i1; v1 = v;  i1 = i; }
    else if (v > v2) { v2 = v;  i2 = i; }
}

// ---------------------------------------------------------------------------
// Kernel 1a: query prep -> qinv + fp16(q_hat)
// ---------------------------------------------------------------------------
__global__ void prep_q_kernel(const float* __restrict__ x)
{
    const int row = blockIdx.x;
    const int tid = threadIdx.x;   // 256
    float4 v = reinterpret_cast<const float4*>(x + (size_t)row * D_)[tid];
    float s = v.x * v.x + v.y * v.y + v.z * v.z + v.w * v.w;
    __shared__ float sm[256];
    sm[tid] = s;
    __syncthreads();
    for (int o = 128; o > 0; o >>= 1) {
        if (tid < o) sm[tid] += sm[tid + o];
        __syncthreads();
    }
    const float inv = 1.0f / fmaxf(sqrtf(sm[0]), 1e-12f);
    if (tid == 0) g_qinv[row] = inv;

    __half2 h0 = __floats2half2_rn(v.x * inv, v.y * inv);
    __half2 h1 = __floats2half2_rn(v.z * inv, v.w * inv);
    uint2 pk;
    pk.x = *reinterpret_cast<uint32_t*>(&h0);
    pk.y = *reinterpret_cast<uint32_t*>(&h1);
    reinterpret_cast<uint2*>(g_qh + (size_t)row * D_)[tid] = pk;
}

// ---------------------------------------------------------------------------
// Kernel 1b: key prep -> kinv + fp16(k_hat)
// ---------------------------------------------------------------------------
__global__ void prep_k_kernel(const float* __restrict__ x)
{
    const int row = blockIdx.x;
    const int tid = threadIdx.x;
    float4 v = reinterpret_cast<const float4*>(x + (size_t)row * D_)[tid];
    float s = v.x * v.x + v.y * v.y + v.z * v.z + v.w * v.w;
    __shared__ float sm[256];
    sm[tid] = s;
    __syncthreads();
    for (int o = 128; o > 0; o >>= 1) {
        if (tid < o) sm[tid] += sm[tid + o];
        __syncthreads();
    }
    const float inv = 1.0f / fmaxf(sqrtf(sm[0]), 1e-12f);
    if (tid == 0) g_kinv[row] = inv;

    __half2 h0 = __floats2half2_rn(v.x * inv, v.y * inv);
    __half2 h1 = __floats2half2_rn(v.z * inv, v.w * inv);
    uint2 pk;
    pk.x = *reinterpret_cast<uint32_t*>(&h0);
    pk.y = *reinterpret_cast<uint32_t*>(&h1);
    reinterpret_cast<uint2*>(g_kh + (size_t)row * D_)[tid] = pk;
}

// ---------------------------------------------------------------------------
// Kernel 2: mma.sync fp16 GEMM (128x128 tile) + fused top3/sum/sumsq
// ---------------------------------------------------------------------------
__global__ __launch_bounds__(256, 2)
void sim_kernel()
{
    extern __shared__ char dynsmem[];
    const uint32_t sbase = smem_u32(dynsmem);

    const int tid = threadIdx.x;
    const int l   = tid & 31;
    const int wid = tid >> 5;
    const int wm  = wid >> 2;      // 0..1
    const int wn  = wid & 3;       // 0..3
    const int nblk = blockIdx.x;
    const int bblk = blockIdx.y;

    const char* srcA = (const char*)(g_qh + (size_t)bblk * BM * D_);
    const char* srcB = (const char*)(g_kh + (size_t)nblk * BN * D_);

    // ---- async tile loader (32 KB per chunk) ------------------------------
    auto load_chunk = [&](int c, int st) {
        const uint32_t stb = sbase + st * STAGE_B;
        const char* srcs[2] = {srcA, srcB};
#pragma unroll
        for (int i = 0; i < 8; i++) {
            const int t = i >> 2;
            const int w = (i & 3) * 256 + tid;
            const int r = w >> 3;
            const int j = w & 7;
            const char* g = srcs[t] + (size_t)r * (D_ * 2) + c * 128 + j * 16;
            uint32_t off = (uint32_t)(r * 128 + j * 16);
            uint32_t dst = stb + t * TILE_B + (off ^ ((off >> 3) & 0x70));
            asm volatile("cp.async.cg.shared.global [%0], [%1], 16;" :: "r"(dst), "l"(g));
        }
        asm volatile("cp.async.commit_group;" ::: "memory");
    };

    // ---- per-lane ldmatrix offsets ----------------------------------------
    const uint32_t rowA = l & 15;
    const uint32_t acs  = (l >> 4) * 16;
    const uint32_t xa   = (rowA & 7) << 4;
    const uint32_t aoff = rowA * 128 + (uint32_t)wm * 8192;   // wm*64 rows

    const uint32_t rowB = (l & 7) + ((l >> 4) << 3);
    const uint32_t bcs  = ((l >> 3) & 1) * 16;
    const uint32_t xb   = (rowB & 7) << 4;
    const uint32_t boff = rowB * 128 + (uint32_t)wn * 4096;   // wn*32 rows

    float acc[4][4][4];
#pragma unroll
    for (int m = 0; m < 4; m++)
#pragma unroll
        for (int n = 0; n < 4; n++)
#pragma unroll
            for (int e = 0; e < 4; e++) acc[m][n][e] = 0.f;

    load_chunk(0, 0);

    for (int c = 0; c < NCH; c++) {
        const int st = c & 1;
        if (c + 1 < NCH) {
            load_chunk(c + 1, st ^ 1);
            asm volatile("cp.async.wait_group 1;" ::: "memory");
        } else {
            asm volatile("cp.async.wait_group 0;" ::: "memory");
        }
        __syncthreads();

        const uint32_t TBa = sbase + st * STAGE_B + aoff;
        const uint32_t TBb = sbase + st * STAGE_B + TILE_B + boff;

#pragma unroll
        for (int ks = 0; ks < 4; ks++) {
            const uint32_t ka = (32u * ks + acs) ^ xa;
            const uint32_t kb = (32u * ks + bcs) ^ xb;
            uint32_t af[4][4];
#pragma unroll
            for (int m = 0; m < 4; m++) ldsm4(af[m], TBa + m * 2048 + ka);

            uint32_t bf[4][2];
#pragma unroll
            for (int p = 0; p < 2; p++) {
                uint32_t t4[4];
                ldsm4(t4, TBb + p * 2048 + kb);
                bf[2 * p][0] = t4[0]; bf[2 * p][1] = t4[1];
                bf[2 * p + 1][0] = t4[2]; bf[2 * p + 1][1] = t4[3];
            }
#pragma unroll
            for (int m = 0; m < 4; m++)
#pragma unroll
                for (int n = 0; n < 4; n++) mma16816(acc[m][n], af[m], bf[n]);
        }
        __syncthreads();
    }

    // ---- epilogue: per-row sum/sumsq/top3 ---------------------------------
    float* spart = reinterpret_cast<float*>(dynsmem);   // 128 rows x 4 nwarps x 8 f

#pragma unroll
    for (int m = 0; m < 4; m++) {
#pragma unroll
        for (int h = 0; h < 2; h++) {
            float sum = 0.f, sq = 0.f;
            float v0 = -2.f, v1 = -2.f, v2 = -2.f;
            int   i0 = 0, i1 = 0, i2 = 0;
            const int colbase = nblk * BN + wn * 32 + 2 * (l & 3);
#pragma unroll
            for (int n = 0; n < 4; n++) {
#pragma unroll
                for (int e = 0; e < 2; e++) {
                    const float v = acc[m][n][2 * h + e];
                    sum += v;
                    sq = fmaf(v, v, sq);
                    top3_ins(v, colbase + 8 * n + e, v0, i0, v1, i1, v2, i2);
                }
            }
#pragma unroll
            for (int o = 1; o <= 2; o <<= 1) {
                float ov0 = __shfl_xor_sync(0xffffffffu, v0, o);
                float ov1 = __shfl_xor_sync(0xffffffffu, v1, o);
                float ov2 = __shfl_xor_sync(0xffffffffu, v2, o);
                int   oi0 = __shfl_xor_sync(0xffffffffu, i0, o);
                int   oi1 = __shfl_xor_sync(0xffffffffu, i1, o);
                int   oi2 = __shfl_xor_sync(0xffffffffu, i2, o);
                sum += __shfl_xor_sync(0xffffffffu, sum, o);
                sq  += __shfl_xor_sync(0xffffffffu, sq, o);
                top3_ins(ov0, oi0, v0, i0, v1, i1, v2, i2);
                top3_ins(ov1, oi1, v0, i0, v1, i1, v2, i2);
                top3_ins(ov2, oi2, v0, i0, v1, i1, v2, i2);
            }
            if ((l & 3) == 0) {
                const int rloc = wm * 64 + 16 * m + (l >> 2) + 8 * h;
                float* p = spart + (rloc * 4 + wn) * 8;
                p[0] = sum; p[1] = sq;
                p[2] = v0;  p[3] = v1;  p[4] = v2;
                p[5] = __int_as_float(i0);
                p[6] = __int_as_float(i1);
                p[7] = __int_as_float(i2);
            }
        }
    }
    __syncthreads();

    if (tid < 128) {
        float sum = 0.f, sq = 0.f;
        float v0 = -2.f, v1 = -2.f, v2 = -2.f;
        int   i0 = 0, i1 = 0, i2 = 0;
#pragma unroll
        for (int w = 0; w < 4; w++) {
            const float* p = spart + (tid * 4 + w) * 8;
            sum += p[0]; sq += p[1];
            top3_ins(p[2], __float_as_int(p[5]), v0, i0, v1, i1, v2, i2);
            top3_ins(p[3], __float_as_int(p[6]), v0, i0, v1, i1, v2, i2);
            top3_ins(p[4], __float_as_int(p[7]), v0, i0, v1, i1, v2, i2);
        }
        const int gr = bblk * BM + tid;
        const size_t o = (size_t)gr * NBLK + nblk;
        g_ms[o]   = make_float2(sum, sq);
        g_topA[o] = make_float4(v0, __int_as_float(i0), v1, __int_as_float(i1));
        g_topB[o] = make_float2(v2, __int_as_float(i2));
    }
}

// ---------------------------------------------------------------------------
// Kernel 3: reduce 256 block-partials per row -> variance + global top-3
// ---------------------------------------------------------------------------
__global__ void finalize_kernel()
{
    const int row = blockIdx.x;
    const int tid = threadIdx.x;   // 256 == NBLK

    __shared__ float4 sA[256];
    __shared__ float2 sB[256];
    __shared__ float2 sM[256];
    const size_t o = (size_t)row * NBLK + tid;
    sA[tid] = g_topA[o];
    sB[tid] = g_topB[o];
    sM[tid] = g_ms[o];
    __syncthreads();

    for (int off = 128; off > 0; off >>= 1) {
        if (tid < off) {
            float4 a = sA[tid]; float2 a2 = sB[tid];
            float4 b = sA[tid + off]; float2 b2 = sB[tid + off];
            float v0 = a.x, v1 = a.z, v2 = a2.x;
            int   i0 = __float_as_int(a.y), i1 = __float_as_int(a.w),
                  i2 = __float_as_int(a2.y);
            top3_ins(b.x,  __float_as_int(b.y),  v0, i0, v1, i1, v2, i2);
            top3_ins(b.z,  __float_as_int(b.w),  v0, i0, v1, i1, v2, i2);
            top3_ins(b2.x, __float_as_int(b2.y), v0, i0, v1, i1, v2, i2);
            sA[tid] = make_float4(v0, __int_as_float(i0), v1, __int_as_float(i1));
            sB[tid] = make_float2(v2, __int_as_float(i2));
            float2 x = sM[tid], y = sM[tid + off];
            sM[tid] = make_float2(x.x + y.x, x.y + y.y);
        }
        __syncthreads();
    }
    if (tid == 0) {
        const float s = sM[0].x, q2 = sM[0].y;
        g_var[row] = (q2 - s * s / (float)N_) / (float)(N_ - 1);
        g_cand[row] = make_int4(__float_as_int(sA[0].y), __float_as_int(sA[0].w),
                                __float_as_int(sB[0].y), 0);
    }
}

// ---------------------------------------------------------------------------
// Kernel 4: exact fp32 rescore of 3 candidates + gather values[best]
// ---------------------------------------------------------------------------
__global__ void rescore_kernel(const float* __restrict__ Q, const float* __restrict__ K,
                               const float* __restrict__ V, float* __restrict__ out)
{
    const int row = blockIdx.x;
    const int tid = threadIdx.x;   // 256
    const int4 cd = g_cand[row];
    const float qi = g_qinv[row];

    float4 q = reinterpret_cast<const float4*>(Q + (size_t)row * D_)[tid];
    q.x *= qi; q.y *= qi; q.z *= qi; q.w *= qi;

    __shared__ float r[3][256];
    __shared__ int sbest;
    const int cands[3] = {cd.x, cd.y, cd.z};
#pragma unroll
    for (int c = 0; c < 3; c++) {
        const float ki = g_kinv[cands[c]];
        float4 k = reinterpret_cast<const float4*>(K + (size_t)cands[c] * D_)[tid];
        r[c][tid] = (q.x * k.x + q.y * k.y + q.z * k.z + q.w * k.w) * ki;
    }
    __syncthreads();
    for (int off = 128; off > 0; off >>= 1) {
        if (tid < off) {
            r[0][tid] += r[0][tid + off];
            r[1][tid] += r[1][tid + off];
            r[2][tid] += r[2][tid + off];
        }
        __syncthreads();
    }
    if (tid == 0) {
        float bv = r[0][0]; int bi = cands[0];
        for (int c = 1; c < 3; c++) {
            const float v = r[c][0];
            if (v > bv || (v == bv && cands[c] < bi)) { bv = v; bi = cands[c]; }
        }
        sbest = bi;
    }
    __syncthreads();
    reinterpret_cast<float4*>(out + (size_t)row * D_)[tid] =
        reinterpret_cast<const float4*>(V + (size_t)sbest * D_)[tid];
}

// ---------------------------------------------------------------------------
// Kernel 5: deterministic mean of row variances -> out[B*D]
// ---------------------------------------------------------------------------
__global__ void var_mean_kernel(float* __restrict__ out)
{
    __shared__ float sm[1024];
    const int tid = threadIdx.x;
    sm[tid] = g_var[tid] + g_var[tid + 1024] + g_var[tid + 2048] + g_var[tid + 3072];
    __syncthreads();
    for (int o = 512; o > 0; o >>= 1) {
        if (tid < o) sm[tid] += sm[tid + o];
        __syncthreads();
    }
    if (tid == 0) out[(size_t)B_ * D_] = sm[0] / (float)B_;
}

// ---------------------------------------------------------------------------
extern "C" void kernel_launch(void* const* d_in, const int* in_sizes, int n_in,
                              void* d_out, int out_size)
{
    const float* query  = (const float*)d_in[0];
    const float* keys   = (const float*)d_in[1];
    const float* values = (const float*)d_in[2];
    float* out = (float*)d_out;

    cudaFuncSetAttribute(sim_kernel, cudaFuncAttributeMaxDynamicSharedMemorySize, SMEM_DYN);

    prep_q_kernel<<<B_, 256>>>(query);
    prep_k_kernel<<<N_, 256>>>(keys);

    sim_kernel<<<dim3(NBLK, BBLK), 256, SMEM_DYN>>>();

    finalize_kernel<<<B_, 256>>>();
    rescore_kernel<<<B_, 256>>>(query, keys, values, out);
    var_mean_kernel<<<1, 1024>>>(out);
}